// round 8
// baseline (speedup 1.0000x reference)
#include <cuda_runtime.h>
#include <cstdint>
#include <math_constants.h>

// OpeningLoss2D: mean((x - grey_opening_2x2(x))^2) over [8,16,512,512] fp32.
// Separable hmin2 -> vmin2 -> hmax2 -> vmax2 (scipy w=2, edge replicate,
// er-index clamps on dilation).
//
// Block-wide 512x64 tile. cp.async ring: 16 row slots, 4 rows per group,
// 3 groups (12 rows) in flight; one wait/barrier/commit per 4 rows.
// Horizontal halo via shuffles + predicated lane-0/31 smem reads; col-512
// sentinel = -inf makes the W-1 dilation clamp predicate-free.

#define FULLMASK 0xffffffffu

static const int Hc = 512;
static const int Wc = 512;
static const int TR = 64;
static const int NBLK = 1024;          // 128 slices * 8 row-tiles
static const int ROWP = 520;           // slot stride (floats), 16B aligned
                                       // ring: 16 slots = 33.3 KB

__device__ float g_partials[NBLK];
__device__ unsigned int g_count = 0;

__device__ __forceinline__ void cp_async16(uint32_t saddr, const float* gaddr) {
    asm volatile("cp.async.cg.shared.global [%0], [%1], 16;\n"
                 :: "r"(saddr), "l"(gaddr));
}
__device__ __forceinline__ void cp_commit() {
    asm volatile("cp.async.commit_group;\n" ::: "memory");
}
template <int N>
__device__ __forceinline__ void cp_wait() {
    asm volatile("cp.async.wait_group %0;\n" :: "n"(N) : "memory");
}

__global__ void __launch_bounds__(128, 6)
opening_kernel(const float* __restrict__ X, float* __restrict__ out) {
    __shared__ float ring[16][ROWP];      // data at [0..511], sentinel at 512
    __shared__ float wsum[4];
    __shared__ bool amLast;

    const int t      = threadIdx.x;       // 0..127
    const int lane   = t & 31;
    const int warpId = t >> 5;
    const int tile   = blockIdx.x;        // 0..1023
    const int slice  = tile >> 3;         // 0..127
    const int r0     = (tile & 7) * TR;
    const float* S   = X + (size_t)slice * (Hc * Wc);
    const int c0     = t << 2;            // first owned column (0..508)
    const bool isL0  = (lane == 0);
    const bool isL31 = (lane == 31);
    const int lcol   = max(c0 - 1, 0);    // left clamp (t=0 -> col 0)
    const int rcol   = c0 + 4;            // t=127 -> col 512 = -inf sentinel

    if (t < 16) ring[t][512] = -CUDART_INF_F;  // er right-edge clamp sentinel

    const uint32_t sring =
        (uint32_t)__cvta_generic_to_shared(&ring[0][0]) + (uint32_t)(c0 * 4);

    // group g covers pipeline rows 4g..4g+3; row p holds x row clamp(r0-1+p)
    #define ISSUE4(g) do {                                                    \
        int _p0 = 4 * (g);                                                    \
        _Pragma("unroll")                                                     \
        for (int _i = 0; _i < 4; ++_i) {                                      \
            int _gr = min(max(r0 - 1 + _p0 + _i, 0), Hc - 1);                 \
            cp_async16(sring + (uint32_t)(((_p0 + _i) & 15) * (ROWP * 4)),    \
                       S + (size_t)_gr * Wc + c0);                            \
        }                                                                     \
    } while (0)

    #define LOADROW(pp)                                                       \
        const float* _row = &ring[(pp) & 15][0];                              \
        float4 _q = *reinterpret_cast<const float4*>(_row + c0);              \
        float _L = __shfl_up_sync(FULLMASK, _q.w, 1);                         \
        float _R = __shfl_down_sync(FULLMASK, _q.x, 1);                       \
        if (isL0)  _L = _row[lcol];                                           \
        if (isL31) _R = _row[rcol];                                           \
        float _h0 = fminf(_L,  _q.x), _h1 = fminf(_q.x, _q.y);                \
        float _h2 = fminf(_q.y, _q.z), _h3 = fminf(_q.z, _q.w);               \
        float _h4 = fminf(_q.w, _R);

    #define FULLROW(pp) do {                                                  \
        LOADROW(pp)                                                            \
        float _e0 = fminf(hp0,_h0), _e1 = fminf(hp1,_h1), _e2 = fminf(hp2,_h2);\
        float _e3 = fminf(hp3,_h3), _e4 = fminf(hp4,_h4);                      \
        float _M0 = fmaxf(_e0,_e1), _M1 = fmaxf(_e1,_e2);                      \
        float _M2 = fmaxf(_e2,_e3), _M3 = fmaxf(_e3,_e4);                      \
        float _s0 = fmaxf(Mp0,_M0), _s1 = fmaxf(Mp1,_M1);                      \
        float _s2 = fmaxf(Mp2,_M2), _s3 = fmaxf(Mp3,_M3);                      \
        float _d0 = xp0 - _s0, _d1 = xp1 - _s1;                                \
        float _d2 = xp2 - _s2, _d3 = xp3 - _s3;                                \
        acc0 = fmaf(_d0,_d0,acc0); acc1 = fmaf(_d1,_d1,acc1);                  \
        acc0 = fmaf(_d2,_d2,acc0); acc1 = fmaf(_d3,_d3,acc1);                  \
        hp0=_h0; hp1=_h1; hp2=_h2; hp3=_h3; hp4=_h4;                           \
        Mp0=_M0; Mp1=_M1; Mp2=_M2; Mp3=_M3;                                    \
        xp0=_q.x; xp1=_q.y; xp2=_q.z; xp3=_q.w;                                \
    } while (0)

    float hp0, hp1, hp2, hp3, hp4;
    float Mp0, Mp1, Mp2, Mp3;
    float xp0, xp1, xp2, xp3;
    float acc0 = 0.f, acc1 = 0.f;

    // prologue: 3 groups (12 rows) in flight
    ISSUE4(0); cp_commit();
    ISSUE4(1); cp_commit();
    ISSUE4(2); cp_commit();

    // step 0 (rows 0..3): peel p=0 (no er), p=1 (no smooth)
    cp_wait<2>();
    __syncthreads();
    ISSUE4(3); cp_commit();
    {   LOADROW(0)
        hp0=_h0; hp1=_h1; hp2=_h2; hp3=_h3; hp4=_h4;
    }
    {   LOADROW(1)
        float _e0 = fminf(hp0,_h0), _e1 = fminf(hp1,_h1), _e2 = fminf(hp2,_h2);
        float _e3 = fminf(hp3,_h3), _e4 = fminf(hp4,_h4);
        Mp0 = fmaxf(_e0,_e1); Mp1 = fmaxf(_e1,_e2);
        Mp2 = fmaxf(_e2,_e3); Mp3 = fmaxf(_e3,_e4);
        hp0=_h0; hp1=_h1; hp2=_h2; hp3=_h3; hp4=_h4;
        xp0=_q.x; xp1=_q.y; xp2=_q.z; xp3=_q.w;
    }
    FULLROW(2);
    FULLROW(3);

    // steps 1..15 (rows 4..63): one wait/barrier/commit per 4 rows
    #pragma unroll 1
    for (int s = 1; s <= 15; ++s) {
        cp_wait<2>();
        __syncthreads();
        if (s + 3 <= 16) ISSUE4(s + 3);
        cp_commit();                       // always: group index tracks step
        FULLROW(4 * s);
        FULLROW(4 * s + 1);
        FULLROW(4 * s + 2);
        FULLROW(4 * s + 3);
    }

    // step 16 (rows 64,65): bottom boundary; rows 66,67 unused
    cp_wait<0>();
    __syncthreads();
    FULLROW(64);
    if (r0 + TR >= Hc) {
        // er row 512 doesn't exist: smooth(511) = hM(511) = Mp
        float _d0 = xp0 - Mp0, _d1 = xp1 - Mp1;
        float _d2 = xp2 - Mp2, _d3 = xp3 - Mp3;
        acc0 = fmaf(_d0,_d0,acc0); acc1 = fmaf(_d1,_d1,acc1);
        acc0 = fmaf(_d2,_d2,acc0); acc1 = fmaf(_d3,_d3,acc1);
    } else {
        FULLROW(65);
    }
    #undef ISSUE4
    #undef LOADROW
    #undef FULLROW

    float acc = acc0 + acc1;
    #pragma unroll
    for (int off = 16; off; off >>= 1)
        acc += __shfl_down_sync(FULLMASK, acc, off);
    if (lane == 0) wsum[warpId] = acc;
    __syncthreads();
    if (t == 0) {
        float s = wsum[0] + wsum[1] + wsum[2] + wsum[3];
        g_partials[blockIdx.x] = s;
        __threadfence();
        unsigned int old = atomicAdd(&g_count, 1u);
        amLast = (old == (unsigned)(NBLK - 1));
    }
    __syncthreads();

    if (amLast) {
        __shared__ float sh[128];
        float s = 0.f;
        for (int i = t; i < NBLK; i += 128) s += g_partials[i];
        sh[t] = s;
        __syncthreads();
        #pragma unroll
        for (int off = 64; off; off >>= 1) {
            if (t < off) sh[t] += sh[t + off];
            __syncthreads();
        }
        if (t == 0) {
            out[0] = sh[0] * (1.0f / 33554432.0f);  // mean over 8*16*512*512
            g_count = 0;                            // deterministic replays
        }
    }
}

extern "C" void kernel_launch(void* const* d_in, const int* in_sizes, int n_in,
                              void* d_out, int out_size) {
    const float* X = (const float*)d_in[0];
    opening_kernel<<<NBLK, 128>>>(X, (float*)d_out);
}

// round 9
// speedup vs baseline: 1.2558x; 1.2558x over previous
#include <cuda_runtime.h>
#include <cstdint>
#include <math_constants.h>

// OpeningLoss2D: mean((x - grey_opening_2x2(x))^2) over [8,16,512,512] fp32.
// Separable hmin2 -> vmin2 -> hmax2 -> vmax2 (scipy w=2, edge replicate,
// er-index clamps on dilation).
//
// R5 structure (best known): block-wide 512x64 tile, cp.async ring of 8 row
// slots, 2 rows/group, 3 groups in flight, shuffle halo + predicated lane-0/31
// smem reads, col-512 -inf sentinel. This round: interior row-tiles (6/8) are
// compile-time specialized clamp-free with a running global pointer so all
// load addresses fold to immediate offsets; hot loop unrolled 4 so ring-slot
// offsets are immediates.

#define FULLMASK 0xffffffffu

static const int Hc = 512;
static const int Wc = 512;
static const int TR = 64;
static const int NBLK = 1024;          // 128 slices * 8 row-tiles
static const int ROWP = 520;           // slot stride (floats), 16B aligned

__device__ float g_partials[NBLK];
__device__ unsigned int g_count = 0;

__device__ __forceinline__ void cp_async16(uint32_t saddr, const float* gaddr) {
    asm volatile("cp.async.cg.shared.global [%0], [%1], 16;\n"
                 :: "r"(saddr), "l"(gaddr));
}
__device__ __forceinline__ void cp_commit() {
    asm volatile("cp.async.commit_group;\n" ::: "memory");
}
template <int N>
__device__ __forceinline__ void cp_wait() {
    asm volatile("cp.async.wait_group %0;\n" :: "n"(N) : "memory");
}

// Processes one 512 x 64 tile; returns this thread's squared-error partial.
// INTERIOR: r0 in [64, 384] -> no row clamps anywhere (incl. overrun groups).
template <bool INTERIOR>
__device__ __forceinline__ float process_tile(
    const float* __restrict__ S, float (*ring)[ROWP], uint32_t sring,
    int r0, int c0, bool isL0, bool isL31, int lcol, int rcol)
{
    // Row p holds x row clamp(r0-1+p). Interior: row p = gp + p*Wc.
    const float* gp = S + (size_t)(INTERIOR ? (r0 - 1) : 0) * Wc + c0;

    #define ISSUE2(g) do {                                                    \
        int _p0 = 2 * (g);                                                    \
        if (INTERIOR) {                                                       \
            cp_async16(sring + (uint32_t)((( _p0)     & 7) * (ROWP * 4)),     \
                       gp + (size_t)_p0 * Wc);                                \
            cp_async16(sring + (uint32_t)(((_p0 + 1) & 7) * (ROWP * 4)),      \
                       gp + (size_t)(_p0 + 1) * Wc);                          \
        } else {                                                              \
            int _g0 = min(max(r0 - 1 + _p0, 0), Hc - 1);                      \
            int _g1 = min(r0 + _p0, Hc - 1);                                  \
            cp_async16(sring + (uint32_t)((( _p0)     & 7) * (ROWP * 4)),     \
                       S + (size_t)_g0 * Wc + c0);                            \
            cp_async16(sring + (uint32_t)(((_p0 + 1) & 7) * (ROWP * 4)),      \
                       S + (size_t)_g1 * Wc + c0);                            \
        }                                                                     \
    } while (0)

    #define LOADROW(pp)                                                       \
        const float* _row = &ring[(pp) & 7][0];                               \
        float4 _q = *reinterpret_cast<const float4*>(_row + c0);              \
        float _L = __shfl_up_sync(FULLMASK, _q.w, 1);                         \
        float _R = __shfl_down_sync(FULLMASK, _q.x, 1);                       \
        if (isL0)  _L = _row[lcol];                                           \
        if (isL31) _R = _row[rcol];                                           \
        float _h0 = fminf(_L,  _q.x), _h1 = fminf(_q.x, _q.y);                \
        float _h2 = fminf(_q.y, _q.z), _h3 = fminf(_q.z, _q.w);               \
        float _h4 = fminf(_q.w, _R);

    #define FULLROW(pp) do {                                                  \
        LOADROW(pp)                                                            \
        float _e0 = fminf(hp0,_h0), _e1 = fminf(hp1,_h1), _e2 = fminf(hp2,_h2);\
        float _e3 = fminf(hp3,_h3), _e4 = fminf(hp4,_h4);                      \
        float _M0 = fmaxf(_e0,_e1), _M1 = fmaxf(_e1,_e2);                      \
        float _M2 = fmaxf(_e2,_e3), _M3 = fmaxf(_e3,_e4);                      \
        float _s0 = fmaxf(Mp0,_M0), _s1 = fmaxf(Mp1,_M1);                      \
        float _s2 = fmaxf(Mp2,_M2), _s3 = fmaxf(Mp3,_M3);                      \
        float _d0 = xp0 - _s0, _d1 = xp1 - _s1;                                \
        float _d2 = xp2 - _s2, _d3 = xp3 - _s3;                                \
        acc0 = fmaf(_d0,_d0,acc0); acc1 = fmaf(_d1,_d1,acc1);                  \
        acc0 = fmaf(_d2,_d2,acc0); acc1 = fmaf(_d3,_d3,acc1);                  \
        hp0=_h0; hp1=_h1; hp2=_h2; hp3=_h3; hp4=_h4;                           \
        Mp0=_M0; Mp1=_M1; Mp2=_M2; Mp3=_M3;                                    \
        xp0=_q.x; xp1=_q.y; xp2=_q.z; xp3=_q.w;                                \
    } while (0)

    float hp0, hp1, hp2, hp3, hp4;
    float Mp0, Mp1, Mp2, Mp3;
    float xp0, xp1, xp2, xp3;
    float acc0 = 0.f, acc1 = 0.f;

    #pragma unroll
    for (int g = 0; g < 3; ++g) { ISSUE2(g); cp_commit(); }

    // step 0 (rows 0,1) peeled: no er at p=0, no smooth at p=1
    cp_wait<2>();
    __syncthreads();
    ISSUE2(3);
    cp_commit();
    {   LOADROW(0)
        hp0=_h0; hp1=_h1; hp2=_h2; hp3=_h3; hp4=_h4;
    }
    {   LOADROW(1)
        float _e0 = fminf(hp0,_h0), _e1 = fminf(hp1,_h1), _e2 = fminf(hp2,_h2);
        float _e3 = fminf(hp3,_h3), _e4 = fminf(hp4,_h4);
        Mp0 = fmaxf(_e0,_e1); Mp1 = fmaxf(_e1,_e2);
        Mp2 = fmaxf(_e2,_e3); Mp3 = fmaxf(_e3,_e4);
        hp0=_h0; hp1=_h1; hp2=_h2; hp3=_h3; hp4=_h4;
        xp0=_q.x; xp1=_q.y; xp2=_q.z; xp3=_q.w;
    }

    // hot loop: steps 1..31 (rows 2..63). Unroll 4 => slot offsets immediate.
    // Overrun groups write slots consumed >= 2 steps earlier (safe, as R5).
    #pragma unroll 4
    for (int s = 1; s <= 31; ++s) {
        cp_wait<2>();
        __syncthreads();
        ISSUE2(s + 3);
        cp_commit();
        FULLROW(2 * s);
        FULLROW(2 * s + 1);
    }

    // step 32 (rows 64,65): bottom boundary
    cp_wait<0>();
    __syncthreads();
    FULLROW(64);
    if (INTERIOR || r0 + TR < Hc) {
        FULLROW(65);
    } else {
        // er row 512 doesn't exist: smooth(511) = hM(511) = Mp
        float _d0 = xp0 - Mp0, _d1 = xp1 - Mp1;
        float _d2 = xp2 - Mp2, _d3 = xp3 - Mp3;
        acc0 = fmaf(_d0,_d0,acc0); acc1 = fmaf(_d1,_d1,acc1);
        acc0 = fmaf(_d2,_d2,acc0); acc1 = fmaf(_d3,_d3,acc1);
    }
    #undef ISSUE2
    #undef LOADROW
    #undef FULLROW

    return acc0 + acc1;
}

__global__ void __launch_bounds__(128, 10)
opening_kernel(const float* __restrict__ X, float* __restrict__ out) {
    __shared__ float ring[8][ROWP];       // ~16.6 KB; data [0..511], sentinel 512
    __shared__ float wsum[4];
    __shared__ bool amLast;

    const int t      = threadIdx.x;       // 0..127
    const int lane   = t & 31;
    const int warpId = t >> 5;
    const int tile   = blockIdx.x;        // 0..1023
    const int slice  = tile >> 3;         // 0..127
    const int r0     = (tile & 7) * TR;
    const float* S   = X + (size_t)slice * (Hc * Wc);
    const int c0     = t << 2;            // first owned column (0..508)
    const bool isL0  = (lane == 0);
    const bool isL31 = (lane == 31);
    const int lcol   = max(c0 - 1, 0);    // left clamp (t=0 -> col 0)
    const int rcol   = c0 + 4;            // t=127 -> col 512 = -inf sentinel

    if (t < 8) ring[t][512] = -CUDART_INF_F;

    const uint32_t sring =
        (uint32_t)__cvta_generic_to_shared(&ring[0][0]) + (uint32_t)(c0 * 4);

    // Interior: no top clamp (r0>=64) and no bottom clamp even for overrun
    // issues up to row r0+68 (r0<=384 -> 452 <= 511).
    const bool interior = (r0 != 0) && (r0 != (Hc - TR));
    float acc = interior
        ? process_tile<true >(S, ring, sring, r0, c0, isL0, isL31, lcol, rcol)
        : process_tile<false>(S, ring, sring, r0, c0, isL0, isL31, lcol, rcol);

    #pragma unroll
    for (int off = 16; off; off >>= 1)
        acc += __shfl_down_sync(FULLMASK, acc, off);
    if (lane == 0) wsum[warpId] = acc;
    __syncthreads();
    if (t == 0) {
        float s = wsum[0] + wsum[1] + wsum[2] + wsum[3];
        g_partials[blockIdx.x] = s;
        __threadfence();
        unsigned int old = atomicAdd(&g_count, 1u);
        amLast = (old == (unsigned)(NBLK - 1));
    }
    __syncthreads();

    if (amLast) {
        __shared__ float sh[128];
        float s = 0.f;
        for (int i = t; i < NBLK; i += 128) s += g_partials[i];
        sh[t] = s;
        __syncthreads();
        #pragma unroll
        for (int off = 64; off; off >>= 1) {
            if (t < off) sh[t] += sh[t + off];
            __syncthreads();
        }
        if (t == 0) {
            out[0] = sh[0] * (1.0f / 33554432.0f);  // mean over 8*16*512*512
            g_count = 0;                            // deterministic replays
        }
    }
}

extern "C" void kernel_launch(void* const* d_in, const int* in_sizes, int n_in,
                              void* d_out, int out_size) {
    const float* X = (const float*)d_in[0];
    opening_kernel<<<NBLK, 128>>>(X, (float*)d_out);
}